// round 5
// baseline (speedup 1.0000x reference)
#include <cuda_runtime.h>
#include <math.h>

#define NDIM 768
#define FDIM 128
#define HDIM 128
#define NN (NDIM*NDIM)

// scratch (no cudaMalloc allowed)
__device__ float g_Xc[2*2*NDIM*64];   // [b][ch][i][d]

// packed 2xfp32 FMA (sm_100+); bit-identical to two scalar fmaf (RN)
union F2U { float2 f; unsigned long long u; };
__device__ __forceinline__ float2 ffma2(float2 a, float2 b, float2 c) {
    F2U A, B, C, D;
    A.f = a; B.f = b; C.f = c;
    asm("fma.rn.f32x2 %0, %1, %2, %3;" : "=l"(D.u) : "l"(A.u), "l"(B.u), "l"(C.u));
    return D.f;
}

__device__ __forceinline__ void cpa16(void* dst_smem, const void* src) {
    unsigned sa = (unsigned)__cvta_generic_to_shared(dst_smem);
    asm volatile("cp.async.cg.shared.global [%0], [%1], 16;\n" :: "r"(sa), "l"(src));
}
#define CP_COMMIT() asm volatile("cp.async.commit_group;\n" ::: "memory")
#define CP_WAIT(n)  asm volatile("cp.async.wait_group %0;\n" :: "n"(n) : "memory")

// ---------------------------------------------------------------------------
// K1: Xc = Xskip + gate * (relu(X@W1+b1)@W2+b2)   (unchanged from R4)
// ---------------------------------------------------------------------------
#define PR_ROWS  4
#define PR_CHUNK 32
#define PR_NCH   (FDIM / PR_CHUNK)   // 4

struct PrepSmem {
    __align__(16) float xs[FDIM][PR_ROWS];
    __align__(16) float hs[HDIM][PR_ROWS];
    __align__(16) float ws[2][PR_CHUNK][HDIM];
};

__device__ __forceinline__ float2 prep_layer(
    const float* __restrict__ W, float bias,
    const float (*in)[PR_ROWS], float ws[2][PR_CHUNK][HDIM], int t)
{
    const int h = t & 127;
    const int s = t >> 7;
    float2 acc = make_float2(bias, bias);

    {
        float* dst = &ws[0][0][0];
        #pragma unroll
        for (int it = 0; it < 4; it++) {
            const int idx = (it * 256 + t) * 4;
            cpa16(dst + idx, W + idx);
        }
        CP_COMMIT();
    }

    #pragma unroll
    for (int c = 0; c < PR_NCH; c++) {
        const int buf = c & 1;
        if (c + 1 < PR_NCH) {
            const float* src = W + (size_t)(c + 1) * PR_CHUNK * HDIM;
            float* dst = &ws[(c + 1) & 1][0][0];
            #pragma unroll
            for (int it = 0; it < 4; it++) {
                const int idx = (it * 256 + t) * 4;
                cpa16(dst + idx, src + idx);
            }
            CP_COMMIT();
            CP_WAIT(1);
        } else {
            CP_WAIT(0);
        }
        __syncthreads();

        #pragma unroll
        for (int fi = 0; fi < PR_CHUNK; fi++) {
            const int f = c * PR_CHUNK + fi;
            const float w = ws[buf][fi][h];
            const float2 xv = *(const float2*)&in[f][2 * s];
            acc = ffma2(xv, make_float2(w, w), acc);
        }
        __syncthreads();
    }
    return acc;
}

__global__ __launch_bounds__(256) void k_prep(
    const float* __restrict__ X,
    const float* __restrict__ w1, const float* __restrict__ b1,
    const float* __restrict__ w2, const float* __restrict__ b2,
    const float* __restrict__ gate)
{
    __shared__ PrepSmem sm;
    const int t = threadIdx.x;
    const int h = t & 127;
    const int s = t >> 7;
    const int row0 = blockIdx.x * PR_ROWS;
    const float g = gate[0];

    {
        const int f = t & 127;
        const int r0 = (t >> 7) * 2;
        sm.xs[f][r0]     = X[(size_t)(row0 + r0) * FDIM + f];
        sm.xs[f][r0 + 1] = X[(size_t)(row0 + r0 + 1) * FDIM + f];
    }

    float2 a1 = prep_layer(w1, b1[h], sm.xs, sm.ws, t);
    sm.hs[h][2 * s]     = fmaxf(a1.x, 0.0f);
    sm.hs[h][2 * s + 1] = fmaxf(a1.y, 0.0f);
    __syncthreads();

    float2 a2 = prep_layer(w2, b2[h], sm.hs, sm.ws, t);

    const int b  = row0 / NDIM;
    const int ch = h & 1;
    const int d  = h >> 1;
    const int i0 = (row0 % NDIM) + 2 * s;
    float* dst = g_Xc + ((size_t)(b * 2 + ch) * NDIM + i0) * 64 + d;
    dst[0]  = sm.xs[h][2 * s]     + g * a2.x;
    dst[64] = sm.xs[h][2 * s + 1] + g * a2.y;
}

// ---------------------------------------------------------------------------
// K2 (fused): per 64x32 upper tile: gram (both channels, channel-packed) +
// per-edge MLP + gumbel decision + coalesced symmetric writes.
// grid = 2 batches x 156 tiles = 312 blocks x 256 threads.
// dynamic smem: As[64][66] float2 (33792B) + Bs[64][34] float2 (17408B);
// vt[64][33] float overlays Bs after gram.
// ---------------------------------------------------------------------------
#define AS_BYTES (64*66*8)
#define BS_BYTES (64*34*8)
#define FUSED_SMEM (AS_BYTES + BS_BYTES)   // 51200

__global__ __launch_bounds__(256) void k_fused(
    const float* __restrict__ sw1, const float* __restrict__ sb1,
    const float* __restrict__ sw2, const float* __restrict__ sb2,
    const float* __restrict__ gumbel, float* __restrict__ out)
{
    extern __shared__ char dynsm[];
    float2 (*As)[66] = (float2(*)[66])dynsm;              // [d][i] (ch0,ch1)
    float2 (*Bs)[34] = (float2(*)[34])(dynsm + AS_BYTES); // [d][j] (ch0,ch1)
    float  (*vt)[33] = (float (*)[33])(dynsm + AS_BYTES); // overlays Bs

    __shared__ __align__(16) float4 wab[HDIM];  // (a,a,b,b)
    __shared__ __align__(16) float4 wcd[HDIM];  // (c,c,w,w)

    const int t = threadIdx.x;

    // decode tile
    int idx = blockIdx.x;
    int b = 0;
    if (idx >= 156) { b = 1; idx -= 156; }
    int bi = 0;
    while (idx >= 24 - 2 * bi) { idx -= 24 - 2 * bi; bi++; }
    const int bj2 = 2 * bi + idx;
    const int i0 = bi * 64;
    const int j0 = bj2 * 32;
    const bool diag = (bj2 <= 2 * bi + 1);

    // stage weights
    if (t < HDIM) {
        const float a  = sw1[t];
        const float bb = sw1[HDIM + t];
        const float c  = sb1[t];
        const float w  = sw2[t * 2 + 1] - sw2[t * 2];
        wab[t] = make_float4(a, a, bb, bb);
        wcd[t] = make_float4(c, c, w, w);
    }

    // stage Xc tiles, channel-interleaved
    const size_t choff = (size_t)NDIM * 64;
    const float* X0 = g_Xc + (size_t)b * 2 * choff;
    for (int k = t; k < 64 * 64; k += 256) {
        const int i = k >> 6, d = k & 63;
        const size_t off = (size_t)(i0 + i) * 64 + d;
        As[d][i] = make_float2(X0[off], X0[choff + off]);
    }
    for (int k = t; k < 32 * 64; k += 256) {
        const int j = k >> 6, d = k & 63;
        const size_t off = (size_t)(j0 + j) * 64 + d;
        Bs[d][j] = make_float2(X0[off], X0[choff + off]);
    }
    __syncthreads();

    // gram: micro-tile 4i x 2j per thread, channels packed in float2
    const int tx = t & 15;   // j-pair: j = j0 + tx*2 + c
    const int ty = t >> 4;   // i-quad: i = i0 + ty*4 + a
    float2 p[4][2];
    #pragma unroll
    for (int a = 0; a < 4; a++) { p[a][0] = make_float2(0.f, 0.f); p[a][1] = make_float2(0.f, 0.f); }

    #pragma unroll 16
    for (int d = 0; d < 64; d++) {
        const float4 a01 = *(const float4*)&As[d][ty * 4];
        const float4 a23 = *(const float4*)&As[d][ty * 4 + 2];
        const float4 bq  = *(const float4*)&Bs[d][tx * 2];
        const float2 b0 = make_float2(bq.x, bq.y);
        const float2 b1 = make_float2(bq.z, bq.w);
        const float2 av[4] = { make_float2(a01.x, a01.y), make_float2(a01.z, a01.w),
                               make_float2(a23.x, a23.y), make_float2(a23.z, a23.w) };
        #pragma unroll
        for (int a = 0; a < 4; a++) {
            p[a][0] = ffma2(av[a], b0, p[a][0]);
            p[a][1] = ffma2(av[a], b1, p[a][1]);
        }
    }
    __syncthreads();   // all As/Bs reads done (vt overlays Bs)

    // repack: q0[a] = (P0 at j+0, P0 at j+1), q1[a] = (P1 ...)
    float2 q0[4], q1[4];
    #pragma unroll
    for (int a = 0; a < 4; a++) {
        q0[a] = make_float2(p[a][0].x, p[a][1].x);
        q1[a] = make_float2(p[a][0].y, p[a][1].y);
    }

    // edge MLP (same op order as previous passing kernel -> bit-identical)
    float2 acc[4];
    #pragma unroll
    for (int a = 0; a < 4; a++) acc[a] = make_float2(0.0f, 0.0f);

    #pragma unroll 4
    for (int h = 0; h < HDIM; h++) {
        const float4 qab = wab[h];
        const float4 qcd = wcd[h];
        const float2 a2 = make_float2(qab.x, qab.y);
        const float2 b2 = make_float2(qab.z, qab.w);
        const float2 c2 = make_float2(qcd.x, qcd.y);
        const float2 w2 = make_float2(qcd.z, qcd.w);
        #pragma unroll
        for (int a = 0; a < 4; a++) {
            float2 pre = ffma2(a2, q0[a], ffma2(b2, q1[a], c2));
            pre.x = fmaxf(pre.x, 0.0f);
            pre.y = fmaxf(pre.y, 0.0f);
            acc[a] = ffma2(w2, pre, acc[a]);
        }
    }

    const float bd = sb2[1] - sb2[0];
    const float* G = gumbel + (size_t)b * NN * 2;
    float* O = out + (size_t)b * NN;

    if (!diag) {
        // decision -> vt
        #pragma unroll
        for (int a = 0; a < 4; a++) {
            const int gi = i0 + ty * 4 + a;
            const float4 g4 = *(const float4*)&G[((size_t)gi * NDIM + j0 + tx * 2) * 2];
            const float v0 = ((acc[a].x + bd) + (g4.y - g4.x) > 0.0f) ? 1.0f : 0.0f;
            const float v1 = ((acc[a].y + bd) + (g4.w - g4.z) > 0.0f) ? 1.0f : 0.0f;
            vt[ty * 4 + a][tx * 2]     = v0;
            vt[ty * 4 + a][tx * 2 + 1] = v1;
        }
        __syncthreads();

        // row writes: 64 rows x 32 floats
        {
            const int row = t >> 2;
            const int q   = t & 3;
            float tmp[8];
            #pragma unroll
            for (int k = 0; k < 8; k++) tmp[k] = vt[row][q * 8 + k];
            float* dst = O + (size_t)(i0 + row) * NDIM + j0 + q * 8;
            ((float4*)dst)[0] = make_float4(tmp[0], tmp[1], tmp[2], tmp[3]);
            ((float4*)dst)[1] = make_float4(tmp[4], tmp[5], tmp[6], tmp[7]);
        }
        // mirror writes: 32 rows x 64 floats (transposed read, conflict-free)
        {
            const int row = t >> 3;
            const int oct = t & 7;
            float tmp[8];
            #pragma unroll
            for (int k = 0; k < 8; k++) tmp[k] = vt[oct * 8 + k][row];
            float* dst = O + (size_t)(j0 + row) * NDIM + i0 + oct * 8;
            ((float4*)dst)[0] = make_float4(tmp[0], tmp[1], tmp[2], tmp[3]);
            ((float4*)dst)[1] = make_float4(tmp[4], tmp[5], tmp[6], tmp[7]);
        }
    } else {
        // diagonal-overlap tile: predicated scatter, each cell written once
        #pragma unroll
        for (int a = 0; a < 4; a++) {
            const int gi = i0 + ty * 4 + a;
            const float4 g4 = *(const float4*)&G[((size_t)gi * NDIM + j0 + tx * 2) * 2];
            #pragma unroll
            for (int c = 0; c < 2; c++) {
                const int gj = j0 + tx * 2 + c;
                const float accv = c ? acc[a].y : acc[a].x;
                const float gg0 = c ? g4.z : g4.x;
                const float gg1 = c ? g4.w : g4.y;
                const float v = ((accv + bd) + (gg1 - gg0) > 0.0f) ? 1.0f : 0.0f;
                if (gj > gi) {
                    O[(size_t)gi * NDIM + gj] = v;
                    O[(size_t)gj * NDIM + gi] = v;
                } else if (gj == gi) {
                    O[(size_t)gi * NDIM + gi] = 0.0f;
                }
            }
        }
    }
}

// ---------------------------------------------------------------------------
extern "C" void kernel_launch(void* const* d_in, const int* in_sizes, int n_in,
                              void* d_out, int out_size)
{
    const float* X     = (const float*)d_in[0];
    const float* ef_w1 = (const float*)d_in[1];
    const float* ef_b1 = (const float*)d_in[2];
    const float* ef_w2 = (const float*)d_in[3];
    const float* ef_b2 = (const float*)d_in[4];
    const float* gate  = (const float*)d_in[5];
    const float* sm_w1 = (const float*)d_in[6];
    const float* sm_b1 = (const float*)d_in[7];
    const float* sm_w2 = (const float*)d_in[8];
    const float* sm_b2 = (const float*)d_in[9];
    const float* gumb  = (const float*)d_in[10];
    float* out = (float*)d_out;

    cudaFuncSetAttribute(k_fused, cudaFuncAttributeMaxDynamicSharedMemorySize, FUSED_SMEM);

    k_prep<<<384, 256>>>(X, ef_w1, ef_b1, ef_w2, ef_b2, gate);
    k_fused<<<312, 256, FUSED_SMEM>>>(sm_w1, sm_b1, sm_w2, sm_b2, gumb, out);
}

// round 6
// speedup vs baseline: 1.1884x; 1.1884x over previous
#include <cuda_runtime.h>
#include <math.h>

#define NDIM 768
#define FDIM 128
#define HDIM 128
#define NN (NDIM*NDIM)
#define EUP ((NDIM*(NDIM-1))/2)   // 294528 upper-triangle edges per batch

// scratch (no cudaMalloc allowed)
__device__ float g_Xc[2*2*NDIM*64];   // [b][ch][i][d]
__device__ float g_P[2*2*NN];         // [b][ch][i][j]  (only i<j tiles valid)

// packed 2xfp32 FMA (sm_100+); bit-identical to two scalar fmaf (RN)
union F2U { float2 f; unsigned long long u; };
__device__ __forceinline__ float2 ffma2(float2 a, float2 b, float2 c) {
    F2U A, B, C, D;
    A.f = a; B.f = b; C.f = c;
    asm("fma.rn.f32x2 %0, %1, %2, %3;" : "=l"(D.u) : "l"(A.u), "l"(B.u), "l"(C.u));
    return D.f;
}

__device__ __forceinline__ void cpa16(void* dst_smem, const void* src) {
    unsigned sa = (unsigned)__cvta_generic_to_shared(dst_smem);
    asm volatile("cp.async.cg.shared.global [%0], [%1], 16;\n" :: "r"(sa), "l"(src));
}
#define CP_COMMIT() asm volatile("cp.async.commit_group;\n" ::: "memory")
#define CP_WAIT(n)  asm volatile("cp.async.wait_group %0;\n" :: "n"(n) : "memory")

// ---------------------------------------------------------------------------
// K1: Xc = Xskip + gate * (relu(X@W1+b1)@W2+b2)   (R4 cp.async version)
// ---------------------------------------------------------------------------
#define PR_ROWS  4
#define PR_CHUNK 32
#define PR_NCH   (FDIM / PR_CHUNK)   // 4

struct PrepSmem {
    __align__(16) float xs[FDIM][PR_ROWS];
    __align__(16) float hs[HDIM][PR_ROWS];
    __align__(16) float ws[2][PR_CHUNK][HDIM];
};

__device__ __forceinline__ float2 prep_layer(
    const float* __restrict__ W, float bias,
    const float (*in)[PR_ROWS], float ws[2][PR_CHUNK][HDIM], int t)
{
    const int h = t & 127;
    const int s = t >> 7;
    float2 acc = make_float2(bias, bias);

    {
        float* dst = &ws[0][0][0];
        #pragma unroll
        for (int it = 0; it < 4; it++) {
            const int idx = (it * 256 + t) * 4;
            cpa16(dst + idx, W + idx);
        }
        CP_COMMIT();
    }

    #pragma unroll
    for (int c = 0; c < PR_NCH; c++) {
        const int buf = c & 1;
        if (c + 1 < PR_NCH) {
            const float* src = W + (size_t)(c + 1) * PR_CHUNK * HDIM;
            float* dst = &ws[(c + 1) & 1][0][0];
            #pragma unroll
            for (int it = 0; it < 4; it++) {
                const int idx = (it * 256 + t) * 4;
                cpa16(dst + idx, src + idx);
            }
            CP_COMMIT();
            CP_WAIT(1);
        } else {
            CP_WAIT(0);
        }
        __syncthreads();

        #pragma unroll
        for (int fi = 0; fi < PR_CHUNK; fi++) {
            const int f = c * PR_CHUNK + fi;
            const float w = ws[buf][fi][h];
            const float2 xv = *(const float2*)&in[f][2 * s];
            acc = ffma2(xv, make_float2(w, w), acc);
        }
        __syncthreads();
    }
    return acc;
}

__global__ __launch_bounds__(256) void k_prep(
    const float* __restrict__ X,
    const float* __restrict__ w1, const float* __restrict__ b1,
    const float* __restrict__ w2, const float* __restrict__ b2,
    const float* __restrict__ gate)
{
    __shared__ PrepSmem sm;
    const int t = threadIdx.x;
    const int h = t & 127;
    const int s = t >> 7;
    const int row0 = blockIdx.x * PR_ROWS;
    const float g = gate[0];

    {
        const int f = t & 127;
        const int r0 = (t >> 7) * 2;
        sm.xs[f][r0]     = X[(size_t)(row0 + r0) * FDIM + f];
        sm.xs[f][r0 + 1] = X[(size_t)(row0 + r0 + 1) * FDIM + f];
    }

    float2 a1 = prep_layer(w1, b1[h], sm.xs, sm.ws, t);
    sm.hs[h][2 * s]     = fmaxf(a1.x, 0.0f);
    sm.hs[h][2 * s + 1] = fmaxf(a1.y, 0.0f);
    __syncthreads();

    float2 a2 = prep_layer(w2, b2[h], sm.hs, sm.ws, t);

    const int b  = row0 / NDIM;
    const int ch = h & 1;
    const int d  = h >> 1;
    const int i0 = (row0 % NDIM) + 2 * s;
    float* dst = g_Xc + ((size_t)(b * 2 + ch) * NDIM + i0) * 64 + d;
    dst[0]  = sm.xs[h][2 * s]     + g * a2.x;
    dst[64] = sm.xs[h][2 * s + 1] + g * a2.y;
}

// ---------------------------------------------------------------------------
// K2: gram  (R3 version, unchanged)
// ---------------------------------------------------------------------------
__global__ __launch_bounds__(256) void k_gram()
{
    __shared__ float As[64][68];
    __shared__ float Bs[64][68];
    const int tid = threadIdx.x;
    const int bc  = blockIdx.y;

    int bi = 0, rem = blockIdx.x;
    while (rem >= 12 - bi) { rem -= 12 - bi; bi++; }
    const int bj = bi + rem;

    const float* Xbase = g_Xc + (size_t)bc * NDIM * 64;
    for (int idx = tid; idx < 4096; idx += 256) {
        const int r = idx >> 6, d = idx & 63;
        As[d][r] = Xbase[(bi * 64 + r) * 64 + d];
        Bs[d][r] = Xbase[(bj * 64 + r) * 64 + d];
    }
    __syncthreads();

    const int tx = tid & 15, ty = tid >> 4;
    float2 c2[4][2];
    #pragma unroll
    for (int a = 0; a < 4; a++) {
        c2[a][0] = make_float2(0.0f, 0.0f);
        c2[a][1] = make_float2(0.0f, 0.0f);
    }

    #pragma unroll 8
    for (int d = 0; d < 64; d++) {
        const float4 av = *(const float4*)&As[d][ty * 4];
        const float4 bv = *(const float4*)&Bs[d][tx * 4];
        const float2 b01 = make_float2(bv.x, bv.y);
        const float2 b23 = make_float2(bv.z, bv.w);
        const float aa[4] = {av.x, av.y, av.z, av.w};
        #pragma unroll
        for (int a = 0; a < 4; a++) {
            const float2 a2 = make_float2(aa[a], aa[a]);
            c2[a][0] = ffma2(a2, b01, c2[a][0]);
            c2[a][1] = ffma2(a2, b23, c2[a][1]);
        }
    }

    float* Pp = g_P + (size_t)bc * NN;
    const int i0 = bi * 64 + ty * 4;
    const int j0 = bj * 64 + tx * 4;
    #pragma unroll
    for (int a = 0; a < 4; a++) {
        float4 v = make_float4(c2[a][0].x, c2[a][0].y, c2[a][1].x, c2[a][1].y);
        *(float4*)&Pp[(size_t)(i0 + a) * NDIM + j0] = v;
    }
}

// ---------------------------------------------------------------------------
// K3: per-edge score MLP (R3 version: float2-array weights — best measured)
// ---------------------------------------------------------------------------
__device__ __forceinline__ long cum_edges(int i) {
    return (long)i * (2 * NDIM - 1 - i) / 2;
}

__global__ __launch_bounds__(256) void k_mlp(
    const float* __restrict__ sw1, const float* __restrict__ sb1,
    const float* __restrict__ sw2, const float* __restrict__ sb2,
    const float* __restrict__ gumbel, float* __restrict__ out)
{
    __shared__ float2 wa2[HDIM], wb2[HDIM], wc2[HDIM], wd2[HDIM];
    const int t = threadIdx.x;
    if (t < HDIM) {
        const float a = sw1[t];
        const float bb = sw1[HDIM + t];
        const float c = sb1[t];
        const float w = sw2[t * 2 + 1] - sw2[t * 2];
        wa2[t] = make_float2(a, a);
        wb2[t] = make_float2(bb, bb);
        wc2[t] = make_float2(c, c);
        wd2[t] = make_float2(w, w);
    }
    __syncthreads();
    const float bd = sb2[1] - sb2[0];

    const long gt = (long)blockIdx.x * 256 + t;

    if (gt < 2 * NDIM) {
        const int b = (int)(gt / NDIM), i = (int)(gt % NDIM);
        out[(size_t)b * NN + (size_t)i * (NDIM + 1)] = 0.0f;
    }

    const long e0 = gt * 8;
    if (e0 >= 2L * EUP) return;
    const int b = (e0 >= EUP);
    long e = e0 - (long)b * EUP;

    const double dn = 2.0 * NDIM - 1.0;
    int i = (int)((dn - sqrt(dn * dn - 8.0 * (double)e)) * 0.5);
    if (i < 0) i = 0;
    while (cum_edges(i + 1) <= e) i++;
    while (cum_edges(i) > e) i--;
    int j = i + 1 + (int)(e - cum_edges(i));

    const float* P0 = g_P + (size_t)(b * 2 + 0) * NN;
    const float* P1 = g_P + (size_t)(b * 2 + 1) * NN;

    float2 p02[4], p12[4];
    int ii[8], jj[8];
    {
        int ci = i, cj = j;
        float p0s[8], p1s[8];
        #pragma unroll
        for (int k = 0; k < 8; k++) {
            ii[k] = ci; jj[k] = cj;
            const size_t off = (size_t)ci * NDIM + cj;
            p0s[k] = P0[off];
            p1s[k] = P1[off];
            if (++cj == NDIM) { ci++; cj = ci + 1; }
        }
        #pragma unroll
        for (int kp = 0; kp < 4; kp++) {
            p02[kp] = make_float2(p0s[2 * kp], p0s[2 * kp + 1]);
            p12[kp] = make_float2(p1s[2 * kp], p1s[2 * kp + 1]);
        }
    }

    float2 acc2[4];
    #pragma unroll
    for (int kp = 0; kp < 4; kp++) acc2[kp] = make_float2(0.0f, 0.0f);

    #pragma unroll 4
    for (int h = 0; h < HDIM; h++) {
        const float2 a2 = wa2[h];
        const float2 b2 = wb2[h];
        const float2 c2 = wc2[h];
        const float2 w2 = wd2[h];
        #pragma unroll
        for (int kp = 0; kp < 4; kp++) {
            float2 pre = ffma2(a2, p02[kp], ffma2(b2, p12[kp], c2));
            pre.x = fmaxf(pre.x, 0.0f);
            pre.y = fmaxf(pre.y, 0.0f);
            acc2[kp] = ffma2(w2, pre, acc2[kp]);
        }
    }

    const float* G = gumbel + (size_t)b * NN * 2;
    float* O = out + (size_t)b * NN;
    #pragma unroll
    for (int kp = 0; kp < 4; kp++) {
        #pragma unroll
        for (int half = 0; half < 2; half++) {
            const int k = 2 * kp + half;
            const float accv = half ? acc2[kp].y : acc2[kp].x;
            const float2 g2 = *(const float2*)&G[((size_t)ii[k] * NDIM + jj[k]) * 2];
            const float v = ((accv + bd) + (g2.y - g2.x) > 0.0f) ? 1.0f : 0.0f;
            O[(size_t)ii[k] * NDIM + jj[k]] = v;
            O[(size_t)jj[k] * NDIM + ii[k]] = v;
        }
    }
}

// ---------------------------------------------------------------------------
extern "C" void kernel_launch(void* const* d_in, const int* in_sizes, int n_in,
                              void* d_out, int out_size)
{
    const float* X     = (const float*)d_in[0];
    const float* ef_w1 = (const float*)d_in[1];
    const float* ef_b1 = (const float*)d_in[2];
    const float* ef_w2 = (const float*)d_in[3];
    const float* ef_b2 = (const float*)d_in[4];
    const float* gate  = (const float*)d_in[5];
    const float* sm_w1 = (const float*)d_in[6];
    const float* sm_b1 = (const float*)d_in[7];
    const float* sm_w2 = (const float*)d_in[8];
    const float* sm_b2 = (const float*)d_in[9];
    const float* gumb  = (const float*)d_in[10];
    float* out = (float*)d_out;

    k_prep<<<384, 256>>>(X, ef_w1, ef_b1, ef_w2, ef_b2, gate);
    k_gram<<<dim3(78, 4), 256>>>();
    const int nthreads = (2 * EUP) / 8;               // 73632
    const int nblocks  = (nthreads + 255) / 256;      // 288
    k_mlp<<<nblocks, 256>>>(sm_w1, sm_b1, sm_w2, sm_b2, gumb, out);
}

// round 7
// speedup vs baseline: 1.1892x; 1.0007x over previous
#include <cuda_runtime.h>
#include <math.h>

#define NDIM 768
#define FDIM 128
#define HDIM 128
#define NN (NDIM*NDIM)
#define EUP ((NDIM*(NDIM-1))/2)   // 294528 upper-triangle edges per batch

// scratch (no cudaMalloc allowed)
__device__ float g_Xc[2*2*NDIM*64];   // [b][ch][i][d]
__device__ float g_P[2*2*NN];         // [b][ch][i][j]  (only i<j tiles valid)

// packed 2xfp32 FMA (sm_100+); bit-identical to two scalar fmaf (RN)
union F2U { float2 f; unsigned long long u; };
__device__ __forceinline__ float2 ffma2(float2 a, float2 b, float2 c) {
    F2U A, B, C, D;
    A.f = a; B.f = b; C.f = c;
    asm("fma.rn.f32x2 %0, %1, %2, %3;" : "=l"(D.u) : "l"(A.u), "l"(B.u), "l"(C.u));
    return D.f;
}

__device__ __forceinline__ void cpa16(void* dst_smem, const void* src) {
    unsigned sa = (unsigned)__cvta_generic_to_shared(dst_smem);
    asm volatile("cp.async.cg.shared.global [%0], [%1], 16;\n" :: "r"(sa), "l"(src));
}
#define CP_COMMIT() asm volatile("cp.async.commit_group;\n" ::: "memory")
#define CP_WAIT(n)  asm volatile("cp.async.wait_group %0;\n" :: "n"(n) : "memory")

// ---------------------------------------------------------------------------
// K1: Xc = Xskip + gate * (relu(X@W1+b1)@W2+b2)   (R6 version, unchanged)
// ---------------------------------------------------------------------------
#define PR_ROWS  4
#define PR_CHUNK 32
#define PR_NCH   (FDIM / PR_CHUNK)   // 4

struct PrepSmem {
    __align__(16) float xs[FDIM][PR_ROWS];
    __align__(16) float hs[HDIM][PR_ROWS];
    __align__(16) float ws[2][PR_CHUNK][HDIM];
};

__device__ __forceinline__ float2 prep_layer(
    const float* __restrict__ W, float bias,
    const float (*in)[PR_ROWS], float ws[2][PR_CHUNK][HDIM], int t)
{
    const int h = t & 127;
    const int s = t >> 7;
    float2 acc = make_float2(bias, bias);

    {
        float* dst = &ws[0][0][0];
        #pragma unroll
        for (int it = 0; it < 4; it++) {
            const int idx = (it * 256 + t) * 4;
            cpa16(dst + idx, W + idx);
        }
        CP_COMMIT();
    }

    #pragma unroll
    for (int c = 0; c < PR_NCH; c++) {
        const int buf = c & 1;
        if (c + 1 < PR_NCH) {
            const float* src = W + (size_t)(c + 1) * PR_CHUNK * HDIM;
            float* dst = &ws[(c + 1) & 1][0][0];
            #pragma unroll
            for (int it = 0; it < 4; it++) {
                const int idx = (it * 256 + t) * 4;
                cpa16(dst + idx, src + idx);
            }
            CP_COMMIT();
            CP_WAIT(1);
        } else {
            CP_WAIT(0);
        }
        __syncthreads();

        #pragma unroll
        for (int fi = 0; fi < PR_CHUNK; fi++) {
            const int f = c * PR_CHUNK + fi;
            const float w = ws[buf][fi][h];
            const float2 xv = *(const float2*)&in[f][2 * s];
            acc = ffma2(xv, make_float2(w, w), acc);
        }
        __syncthreads();
    }
    return acc;
}

__global__ __launch_bounds__(256) void k_prep(
    const float* __restrict__ X,
    const float* __restrict__ w1, const float* __restrict__ b1,
    const float* __restrict__ w2, const float* __restrict__ b2,
    const float* __restrict__ gate)
{
    __shared__ PrepSmem sm;
    const int t = threadIdx.x;
    const int h = t & 127;
    const int s = t >> 7;
    const int row0 = blockIdx.x * PR_ROWS;
    const float g = gate[0];

    {
        const int f = t & 127;
        const int r0 = (t >> 7) * 2;
        sm.xs[f][r0]     = X[(size_t)(row0 + r0) * FDIM + f];
        sm.xs[f][r0 + 1] = X[(size_t)(row0 + r0 + 1) * FDIM + f];
    }

    float2 a1 = prep_layer(w1, b1[h], sm.xs, sm.ws, t);
    sm.hs[h][2 * s]     = fmaxf(a1.x, 0.0f);
    sm.hs[h][2 * s + 1] = fmaxf(a1.y, 0.0f);
    __syncthreads();

    float2 a2 = prep_layer(w2, b2[h], sm.hs, sm.ws, t);

    const int b  = row0 / NDIM;
    const int ch = h & 1;
    const int d  = h >> 1;
    const int i0 = (row0 % NDIM) + 2 * s;
    float* dst = g_Xc + ((size_t)(b * 2 + ch) * NDIM + i0) * 64 + d;
    dst[0]  = sm.xs[h][2 * s]     + g * a2.x;
    dst[64] = sm.xs[h][2 * s + 1] + g * a2.y;
}

// ---------------------------------------------------------------------------
// K2: gram  (R6 version, unchanged)
// ---------------------------------------------------------------------------
__global__ __launch_bounds__(256) void k_gram()
{
    __shared__ float As[64][68];
    __shared__ float Bs[64][68];
    const int tid = threadIdx.x;
    const int bc  = blockIdx.y;

    int bi = 0, rem = blockIdx.x;
    while (rem >= 12 - bi) { rem -= 12 - bi; bi++; }
    const int bj = bi + rem;

    const float* Xbase = g_Xc + (size_t)bc * NDIM * 64;
    for (int idx = tid; idx < 4096; idx += 256) {
        const int r = idx >> 6, d = idx & 63;
        As[d][r] = Xbase[(bi * 64 + r) * 64 + d];
        Bs[d][r] = Xbase[(bj * 64 + r) * 64 + d];
    }
    __syncthreads();

    const int tx = tid & 15, ty = tid >> 4;
    float2 c2[4][2];
    #pragma unroll
    for (int a = 0; a < 4; a++) {
        c2[a][0] = make_float2(0.0f, 0.0f);
        c2[a][1] = make_float2(0.0f, 0.0f);
    }

    #pragma unroll 8
    for (int d = 0; d < 64; d++) {
        const float4 av = *(const float4*)&As[d][ty * 4];
        const float4 bv = *(const float4*)&Bs[d][tx * 4];
        const float2 b01 = make_float2(bv.x, bv.y);
        const float2 b23 = make_float2(bv.z, bv.w);
        const float aa[4] = {av.x, av.y, av.z, av.w};
        #pragma unroll
        for (int a = 0; a < 4; a++) {
            const float2 a2 = make_float2(aa[a], aa[a]);
            c2[a][0] = ffma2(a2, b01, c2[a][0]);
            c2[a][1] = ffma2(a2, b23, c2[a][1]);
        }
    }

    float* Pp = g_P + (size_t)bc * NN;
    const int i0 = bi * 64 + ty * 4;
    const int j0 = bj * 64 + tx * 4;
    #pragma unroll
    for (int a = 0; a < 4; a++) {
        float4 v = make_float4(c2[a][0].x, c2[a][0].y, c2[a][1].x, c2[a][1].y);
        *(float4*)&Pp[(size_t)(i0 + a) * NDIM + j0] = v;
    }
}

// ---------------------------------------------------------------------------
// K3: per-edge score MLP — 4 edges/thread (576 blocks, 2x warps vs R6)
// ---------------------------------------------------------------------------
#define MLP_E 4   // edges per thread (must divide EUP, be even)

__device__ __forceinline__ long cum_edges(int i) {
    return (long)i * (2 * NDIM - 1 - i) / 2;
}

__global__ __launch_bounds__(256) void k_mlp(
    const float* __restrict__ sw1, const float* __restrict__ sb1,
    const float* __restrict__ sw2, const float* __restrict__ sb2,
    const float* __restrict__ gumbel, float* __restrict__ out)
{
    __shared__ float2 wa2[HDIM], wb2[HDIM], wc2[HDIM], wd2[HDIM];
    const int t = threadIdx.x;
    if (t < HDIM) {
        const float a = sw1[t];
        const float bb = sw1[HDIM + t];
        const float c = sb1[t];
        const float w = sw2[t * 2 + 1] - sw2[t * 2];
        wa2[t] = make_float2(a, a);
        wb2[t] = make_float2(bb, bb);
        wc2[t] = make_float2(c, c);
        wd2[t] = make_float2(w, w);
    }
    __syncthreads();
    const float bd = sb2[1] - sb2[0];

    const long gt = (long)blockIdx.x * 256 + t;

    if (gt < 2 * NDIM) {
        const int b = (int)(gt / NDIM), i = (int)(gt % NDIM);
        out[(size_t)b * NN + (size_t)i * (NDIM + 1)] = 0.0f;
    }

    const long e0 = gt * MLP_E;
    if (e0 >= 2L * EUP) return;
    const int b = (e0 >= EUP);            // EUP % MLP_E == 0 -> no straddle
    long e = e0 - (long)b * EUP;

    const double dn = 2.0 * NDIM - 1.0;
    int i = (int)((dn - sqrt(dn * dn - 8.0 * (double)e)) * 0.5);
    if (i < 0) i = 0;
    while (cum_edges(i + 1) <= e) i++;
    while (cum_edges(i) > e) i--;
    int j = i + 1 + (int)(e - cum_edges(i));

    const float* P0 = g_P + (size_t)(b * 2 + 0) * NN;
    const float* P1 = g_P + (size_t)(b * 2 + 1) * NN;

    float2 p02[MLP_E / 2], p12[MLP_E / 2];
    int ii[MLP_E], jj[MLP_E];
    {
        int ci = i, cj = j;
        float p0s[MLP_E], p1s[MLP_E];
        #pragma unroll
        for (int k = 0; k < MLP_E; k++) {
            ii[k] = ci; jj[k] = cj;
            const size_t off = (size_t)ci * NDIM + cj;
            p0s[k] = P0[off];
            p1s[k] = P1[off];
            if (++cj == NDIM) { ci++; cj = ci + 1; }
        }
        #pragma unroll
        for (int kp = 0; kp < MLP_E / 2; kp++) {
            p02[kp] = make_float2(p0s[2 * kp], p0s[2 * kp + 1]);
            p12[kp] = make_float2(p1s[2 * kp], p1s[2 * kp + 1]);
        }
    }

    float2 acc2[MLP_E / 2];
    #pragma unroll
    for (int kp = 0; kp < MLP_E / 2; kp++) acc2[kp] = make_float2(0.0f, 0.0f);

    #pragma unroll 4
    for (int h = 0; h < HDIM; h++) {
        const float2 a2 = wa2[h];
        const float2 b2 = wb2[h];
        const float2 c2 = wc2[h];
        const float2 w2 = wd2[h];
        #pragma unroll
        for (int kp = 0; kp < MLP_E / 2; kp++) {
            float2 pre = ffma2(a2, p02[kp], ffma2(b2, p12[kp], c2));
            pre.x = fmaxf(pre.x, 0.0f);
            pre.y = fmaxf(pre.y, 0.0f);
            acc2[kp] = ffma2(w2, pre, acc2[kp]);
        }
    }

    const float* G = gumbel + (size_t)b * NN * 2;
    float* O = out + (size_t)b * NN;
    #pragma unroll
    for (int kp = 0; kp < MLP_E / 2; kp++) {
        #pragma unroll
        for (int half = 0; half < 2; half++) {
            const int k = 2 * kp + half;
            const float accv = half ? acc2[kp].y : acc2[kp].x;
            const float2 g2 = *(const float2*)&G[((size_t)ii[k] * NDIM + jj[k]) * 2];
            const float v = ((accv + bd) + (g2.y - g2.x) > 0.0f) ? 1.0f : 0.0f;
            O[(size_t)ii[k] * NDIM + jj[k]] = v;
            O[(size_t)jj[k] * NDIM + ii[k]] = v;
        }
    }
}

// ---------------------------------------------------------------------------
extern "C" void kernel_launch(void* const* d_in, const int* in_sizes, int n_in,
                              void* d_out, int out_size)
{
    const float* X     = (const float*)d_in[0];
    const float* ef_w1 = (const float*)d_in[1];
    const float* ef_b1 = (const float*)d_in[2];
    const float* ef_w2 = (const float*)d_in[3];
    const float* ef_b2 = (const float*)d_in[4];
    const float* gate  = (const float*)d_in[5];
    const float* sm_w1 = (const float*)d_in[6];
    const float* sm_b1 = (const float*)d_in[7];
    const float* sm_w2 = (const float*)d_in[8];
    const float* sm_b2 = (const float*)d_in[9];
    const float* gumb  = (const float*)d_in[10];
    float* out = (float*)d_out;

    k_prep<<<384, 256>>>(X, ef_w1, ef_b1, ef_w2, ef_b2, gate);
    k_gram<<<dim3(78, 4), 256>>>();
    const int nthreads = (2 * EUP) / MLP_E;               // 147264
    const int nblocks  = (nthreads + 255) / 256;          // 576
    k_mlp<<<nblocks, 256>>>(sm_w1, sm_b1, sm_w2, sm_b2, gumb, out);
}